// round 5
// baseline (speedup 1.0000x reference)
#include <cuda_runtime.h>
#include <math.h>

#define B_  128
#define T_  2048
#define D_  512
#define SPL 16                       // t-splits (tiles) per batch
#define TS  (T_ / SPL)               // 128
#define M1_KS 8                      // split-K for m1 GEMM (K=1024)
#define F2_KS 4                      // split-K for m1@W_m2 (K=512)
#define FS_KS 8                      // split-K for msa@W_s (K=512, 64-wide)

// ---------------- scratch ----------------
__device__ float  g_part[B_ * SPL * D_];     // unnormalized msa partials (4 MB)
__device__ float2 g_stats[B_ * SPL];         // per-tile {local_max, local_expsum}
__device__ float  g_scale[B_ * SPL];         // per-tile softmax rescale
__device__ float  g_m1p[M1_KS][B_ * D_];     // m1 split-K partials
__device__ float  g_f2p[F2_KS][B_ * D_];     // m1@W_m2 partials
__device__ float  g_fsp[FS_KS][B_ * D_];     // msa@W_s partials
__device__ float  g_gate[B_];                // sigmoid gates

// ================= K_A: single-pass stream (+ m1 GEMM + gate blocks) =================
// blocks [0,256): m1 split-K GEMM; [256, 256+2048): fused logits+msa tiles; last: gate.
__global__ __launch_bounds__(256) void kA(const float* __restrict__ past,
                                          const float* __restrict__ control,
                                          const float* __restrict__ W_ca,
                                          const float* __restrict__ b_ca,
                                          const float* __restrict__ memory,
                                          const float* __restrict__ read,
                                          const float* __restrict__ W_m1,
                                          const float* __restrict__ W_m3,
                                          const float* __restrict__ b_m3)
{
    __shared__ __align__(16) float sbuf[8 * 128];   // 4 KB, carved per role
    const int tid = threadIdx.x;
    int bid = blockIdx.x;

    if (bid < 256) {
        // ---- m1 GEMM: g_m1p[ks][b,k] = sum_{jj in slice ks} A[b,jj] * W_m1[jj,k]
        const int ks = bid & 7, bg = (bid >> 3) & 15, st = bid >> 7;
        const int k = st * 256 + tid;
        float (*s_a)[128] = reinterpret_cast<float (*)[128]>(sbuf);   // full 4 KB
        for (int i = tid; i < 8 * 128; i += 256) {
            const int bb = i >> 7, j = i & 127;
            const int jj = ks * 128 + j;
            const int b = bg * 8 + bb;
            s_a[bb][j] = (jj < D_) ? memory[b * D_ + jj] : read[b * D_ + (jj - D_)];
        }
        __syncthreads();
        float acc[8] = {};
        const float* Wb = W_m1 + (size_t)(ks * 128) * D_ + k;
        #pragma unroll 4
        for (int j = 0; j < 128; j++) {
            const float wv = __ldg(&Wb[(size_t)j * D_]);
            #pragma unroll
            for (int bb = 0; bb < 8; bb++) acc[bb] += s_a[bb][j] * wv;
        }
        #pragma unroll
        for (int bb = 0; bb < 8; bb++)
            g_m1p[ks][(size_t)(bg * 8 + bb) * D_ + k] = acc[bb];
        return;
    }
    if (bid == 256 + B_ * SPL) {
        // ---- gate: g_gate[b] = sigmoid(control[b,:]·W_m3 + b_m3)
        const int warp = tid >> 5, lane = tid & 31;
        #pragma unroll
        for (int q = 0; q < 16; q++) {
            const int b = warp * 16 + q;
            float a = 0.f;
            #pragma unroll
            for (int j = 0; j < 16; j++)
                a += control[(size_t)b * D_ + lane + j * 32] * W_m3[lane + j * 32];
            #pragma unroll
            for (int o = 16; o; o >>= 1) a += __shfl_xor_sync(0xffffffffu, a, o);
            if (lane == 0) g_gate[b] = 1.f / (1.f + expf(-(a + b_m3[0])));
        }
        return;
    }

    // ---- fused tile: b, s ----
    // shared carve: [0,512) = c*W_ca (as float4[128]); [512,640) logits; [640,768) weights; [768] red
    float4* s_cw   = reinterpret_cast<float4*>(sbuf);   // 128 float4 = floats [0,512)
    float*  s_logit = sbuf + 512;                       // 128 floats
    float*  s_w     = sbuf + 640;                       // 128 floats
    float*  s_red   = sbuf + 768;

    bid -= 256;
    const int b = bid >> 4, s = bid & 15;
    const int warp = tid >> 5, lane = tid & 31;
    const float* cbase = past + (size_t)b * T_ * (2 * D_) + (size_t)s * TS * (2 * D_);

    if (tid < D_ / 4) {
        float4 c = reinterpret_cast<const float4*>(control + (size_t)b * D_)[tid];
        float4 w = reinterpret_cast<const float4*>(W_ca)[tid];
        s_cw[tid] = make_float4(c.x * w.x, c.y * w.y, c.z * w.z, c.w * w.w);
    }
    __syncthreads();

    // --- phase A: 128 logits (8 warps x 16 t, two groups of 8 for MLP) ---
    const float bias = b_ca[0];
    #pragma unroll
    for (int g = 0; g < 2; g++) {
        const int t0 = warp * 16 + g * 8;
        float acc[8] = {};
        #pragma unroll
        for (int j = 0; j < 4; j++) {
            const float4 c = s_cw[lane + j * 32];
            #pragma unroll
            for (int i = 0; i < 8; i++) {
                float4 v = reinterpret_cast<const float4*>(
                               cbase + (size_t)(t0 + i) * (2 * D_))[lane + j * 32];
                acc[i] += v.x * c.x + v.y * c.y + v.z * c.z + v.w * c.w;
            }
        }
        #pragma unroll
        for (int i = 0; i < 8; i++) {
            float a = acc[i];
            #pragma unroll
            for (int o = 16; o; o >>= 1) a += __shfl_xor_sync(0xffffffffu, a, o);
            if (lane == 0) s_logit[t0 + i] = a + bias;
        }
    }
    __syncthreads();

    // --- local softmax stats over the 128 tile logits (warp 0) ---
    if (warp == 0) {
        float v[4], m = -3.4e38f;
        #pragma unroll
        for (int q = 0; q < 4; q++) {
            float x = s_logit[lane + q * 32];
            if (x == 0.f) x = -1e9f;              // padding mask
            v[q] = x;
            m = fmaxf(m, x);
        }
        #pragma unroll
        for (int o = 16; o; o >>= 1) m = fmaxf(m, __shfl_xor_sync(0xffffffffu, m, o));
        float sum = 0.f;
        #pragma unroll
        for (int q = 0; q < 4; q++) sum += expf(v[q] - m);
        #pragma unroll
        for (int o = 16; o; o >>= 1) sum += __shfl_xor_sync(0xffffffffu, sum, o);
        if (lane == 0) { s_red[0] = m; g_stats[b * SPL + s] = make_float2(m, sum); }
    }
    __syncthreads();
    const float mx = s_red[0];
    if (tid < TS) {
        float x = s_logit[tid];
        if (x == 0.f) x = -1e9f;
        s_w[tid] = expf(x - mx);                  // unnormalized weight
    }
    __syncthreads();

    // --- phase B: weighted sum of memories half (256 threads, float2, ILP 4) ---
    const float2* mbase = reinterpret_cast<const float2*>(cbase + D_);
    float2 a0 = {0,0}, a1 = {0,0}, a2 = {0,0}, a3 = {0,0};
    #pragma unroll 4
    for (int t = 0; t < TS; t += 4) {
        float2 v0 = mbase[(size_t)(t + 0) * D_ + tid];
        float2 v1 = mbase[(size_t)(t + 1) * D_ + tid];
        float2 v2 = mbase[(size_t)(t + 2) * D_ + tid];
        float2 v3 = mbase[(size_t)(t + 3) * D_ + tid];
        const float w0 = s_w[t], w1 = s_w[t + 1], w2 = s_w[t + 2], w3 = s_w[t + 3];
        a0.x += w0 * v0.x; a0.y += w0 * v0.y;
        a1.x += w1 * v1.x; a1.y += w1 * v1.y;
        a2.x += w2 * v2.x; a2.y += w2 * v2.y;
        a3.x += w3 * v3.x; a3.y += w3 * v3.y;
    }
    float2 acc = make_float2((a0.x + a1.x) + (a2.x + a3.x),
                             (a0.y + a1.y) + (a2.y + a3.y));
    reinterpret_cast<float2*>(g_part + (size_t)(b * SPL + s) * D_)[tid] = acc;
}

// ================= K_B: combine per-tile stats into rescale factors =================
__global__ __launch_bounds__(32) void kB()
{
    const int b = blockIdx.x, lane = threadIdx.x;
    float m = -3.4e38f, sm = 0.f;
    if (lane < SPL) {
        float2 st = g_stats[b * SPL + lane];
        m = st.x; sm = st.y;
    }
    float gm = m;
    #pragma unroll
    for (int o = 16; o; o >>= 1) gm = fmaxf(gm, __shfl_xor_sync(0xffffffffu, gm, o));
    float p = (lane < SPL) ? sm * expf(m - gm) : 0.f;
    float tot = p;
    #pragma unroll
    for (int o = 16; o; o >>= 1) tot += __shfl_xor_sync(0xffffffffu, tot, o);
    if (lane < SPL) g_scale[b * SPL + lane] = expf(m - gm) / tot;
}

// ================= K_C: m1@W_m2 GEMM + msa@W_s GEMM (scales applied on load) =================
// blocks [0,128): W_m2 GEMM; [128, 384): W_s GEMM.
__global__ __launch_bounds__(256) void kC(const float* __restrict__ W_m2,
                                          const float* __restrict__ b_m1,
                                          const float* __restrict__ W_s)
{
    __shared__ float smem[8][128];
    const int tid = threadIdx.x;
    int bid = blockIdx.x;

    if (bid < 128) {
        // ---- g_f2p[ks][b,k] = sum_{jj in slice} m1[b,jj] * W_m2[jj,k]
        const int ks = bid & 3, bg = (bid >> 2) & 15, st = bid >> 6;
        const int k = st * 256 + tid;
        for (int i = tid; i < 8 * 128; i += 256) {
            const int bb = i >> 7, j = i & 127;
            const int jj = ks * 128 + j;
            const int b = bg * 8 + bb;
            float m1 = b_m1[jj];
            #pragma unroll
            for (int p = 0; p < M1_KS; p++) m1 += g_m1p[p][(size_t)b * D_ + jj];
            smem[bb][j] = m1;
        }
        __syncthreads();
        float acc[8] = {};
        const float* Wb = W_m2 + (size_t)(ks * 128) * D_ + k;
        #pragma unroll 4
        for (int j = 0; j < 128; j++) {
            const float wv = __ldg(&Wb[(size_t)j * D_]);
            #pragma unroll
            for (int bb = 0; bb < 8; bb++) acc[bb] += smem[bb][j] * wv;
        }
        #pragma unroll
        for (int bb = 0; bb < 8; bb++)
            g_f2p[ks][(size_t)(bg * 8 + bb) * D_ + k] = acc[bb];
        return;
    }

    // ---- g_fsp[ks][b,k] = sum_{jj in 64-slice} msa[b,jj] * W_s[jj,k]
    bid -= 128;
    const int ks = bid & 7, bg = (bid >> 3) & 15, st = bid >> 7;
    const int k = st * 256 + tid;
    float (*s_msa)[64] = reinterpret_cast<float (*)[64]>(smem);
    for (int i = tid; i < 8 * 64; i += 256) {
        const int bb = i >> 6, j = i & 63;
        const int jj = ks * 64 + j;
        const int b = bg * 8 + bb;
        float ms = 0.f;
        #pragma unroll
        for (int sp = 0; sp < SPL; sp++)
            ms += g_part[(size_t)(b * SPL + sp) * D_ + jj] * g_scale[b * SPL + sp];
        s_msa[bb][j] = ms;
    }
    __syncthreads();
    float acc[8] = {};
    const float* Wb = W_s + (size_t)(ks * 64) * D_ + k;
    #pragma unroll 4
    for (int j = 0; j < 64; j++) {
        const float wv = __ldg(&Wb[(size_t)j * D_]);
        #pragma unroll
        for (int bb = 0; bb < 8; bb++) acc[bb] += s_msa[bb][j] * wv;
    }
    #pragma unroll
    for (int bb = 0; bb < 8; bb++)
        g_fsp[ks][(size_t)(bg * 8 + bb) * D_ + k] = acc[bb];
}

// ================= K_D: epilogue =================
__global__ __launch_bounds__(512) void kD(const float* __restrict__ b_m2,
                                          const float* __restrict__ b_s,
                                          const float* __restrict__ memory,
                                          float* __restrict__ out)
{
    const int b = blockIdx.x, k = threadIdx.x;
    float acc = b_m2[k] + b_s[k];
    #pragma unroll
    for (int p = 0; p < F2_KS; p++) acc += g_f2p[p][(size_t)b * D_ + k];
    #pragma unroll
    for (int p = 0; p < FS_KS; p++) acc += g_fsp[p][(size_t)b * D_ + k];
    const float g = g_gate[b];
    out[(size_t)b * D_ + k] = acc * g + (1.f - g) * memory[(size_t)b * D_ + k];
}

// ---------------- launch ----------------
extern "C" void kernel_launch(void* const* d_in, const int* in_sizes, int n_in,
                              void* d_out, int out_size)
{
    const float* memory  = (const float*)d_in[0];
    const float* read    = (const float*)d_in[1];
    const float* control = (const float*)d_in[2];
    const float* past    = (const float*)d_in[3];
    const float* W_m1    = (const float*)d_in[4];
    const float* b_m1    = (const float*)d_in[5];
    const float* W_ca    = (const float*)d_in[6];
    const float* b_ca    = (const float*)d_in[7];
    const float* W_m2    = (const float*)d_in[8];
    const float* b_m2    = (const float*)d_in[9];
    const float* W_s     = (const float*)d_in[10];
    const float* b_s     = (const float*)d_in[11];
    const float* W_m3    = (const float*)d_in[12];
    const float* b_m3    = (const float*)d_in[13];
    float* out = (float*)d_out;

    kA<<<256 + B_ * SPL + 1, 256>>>(past, control, W_ca, b_ca,
                                    memory, read, W_m1, W_m3, b_m3);
    kB<<<B_, 32>>>();
    kC<<<384, 256>>>(W_m2, b_m1, W_s);
    kD<<<B_, 512>>>(b_m2, b_s, memory, out);
}

// round 6
// speedup vs baseline: 1.0761x; 1.0761x over previous
#include <cuda_runtime.h>
#include <math.h>

#define B_  128
#define T_  2048
#define D_  512
#define SPL 16                       // t-splits per batch
#define TS  (T_ / SPL)               // 128
#define M1_KS 8                      // m1 GEMM split-K (K=1024, 128-wide)
#define F2_KS 8                      // m1@W_m2 split-K (K=512, 64-wide)
#define FS_KS 16                     // msa@W_s split-K (K=512, 32-wide)

// block-role layout (blockIdx order == rough scheduling order)
#define BID_GATE   0
#define BID_M1     1                         // [1, 257)
#define BID_F2     (BID_M1 + 256)            // [257, 513)
#define BID_TILE   (BID_F2 + 256)            // [513, 2561)
#define BID_FS     (BID_TILE + B_ * SPL)     // [2561, 3073)
#define BID_EPI    (BID_FS + 512)            // [3073, 3201)
#define GRID_TOTAL (BID_EPI + B_)

// ---------------- scratch ----------------
__device__ float  g_part[B_ * SPL * D_];     // unnormalized msa partials (4 MB)
__device__ float2 g_stats[B_ * SPL];         // per-tile {local_max, local_expsum}
__device__ float  g_m1p[M1_KS][B_ * D_];     // m1 split-K partials
__device__ float  g_f2p[F2_KS][B_ * D_];     // m1@W_m2 partials
__device__ float  g_fsp[FS_KS][B_ * D_];     // msa@W_s partials
__device__ float  g_gate[B_];                // sigmoid gates

// pipeline counters (zero at load; reset by last epilogue block each run)
__device__ int c_m1, c_tile, c_f2, c_fs, c_epi;

__device__ __forceinline__ void block_signal(int* c) {
    __threadfence();
    __syncthreads();
    if (threadIdx.x == 0) atomicAdd(c, 1);
}
__device__ __forceinline__ void block_wait(int* c, int target) {
    if (threadIdx.x == 0) {
        while (atomicAdd(c, 0) < target) __nanosleep(128);
        __threadfence();
    }
    __syncthreads();
}

__global__ __launch_bounds__(256) void kmain(const float* __restrict__ past,
                                             const float* __restrict__ control,
                                             const float* __restrict__ W_ca,
                                             const float* __restrict__ b_ca,
                                             const float* __restrict__ memory,
                                             const float* __restrict__ read,
                                             const float* __restrict__ W_m1,
                                             const float* __restrict__ b_m1,
                                             const float* __restrict__ W_m2,
                                             const float* __restrict__ b_m2,
                                             const float* __restrict__ W_s,
                                             const float* __restrict__ b_s,
                                             const float* __restrict__ W_m3,
                                             const float* __restrict__ b_m3,
                                             float* __restrict__ out)
{
    __shared__ __align__(16) float sbuf[8 * 128 + 8 * 16];   // 4.5 KB, carved per role
    const int tid = threadIdx.x;
    const int bid = blockIdx.x;

    // ================= gate =================
    if (bid == BID_GATE) {
        const int warp = tid >> 5, lane = tid & 31;
        #pragma unroll
        for (int q = 0; q < 16; q++) {
            const int b = warp * 16 + q;
            float a = 0.f;
            #pragma unroll
            for (int j = 0; j < 16; j++)
                a += control[(size_t)b * D_ + lane + j * 32] * W_m3[lane + j * 32];
            #pragma unroll
            for (int o = 16; o; o >>= 1) a += __shfl_xor_sync(0xffffffffu, a, o);
            if (lane == 0) g_gate[b] = 1.f / (1.f + expf(-(a + b_m3[0])));
        }
        block_signal(&c_f2);       // epilogue waits c_f2 == 257 (256 F2 + gate)
        return;
    }

    // ================= m1 GEMM (split-K 8, 128-wide) =================
    if (bid < BID_F2) {
        const int idx = bid - BID_M1;
        const int ks = idx & 7, bg = (idx >> 3) & 15, st = idx >> 7;
        const int k = st * 256 + tid;
        float (*s_a)[128] = reinterpret_cast<float (*)[128]>(sbuf);
        for (int i = tid; i < 8 * 128; i += 256) {
            const int bb = i >> 7, j = i & 127;
            const int jj = ks * 128 + j;
            const int b = bg * 8 + bb;
            s_a[bb][j] = (jj < D_) ? memory[b * D_ + jj] : read[b * D_ + (jj - D_)];
        }
        __syncthreads();
        float acc[8] = {};
        const float* Wb = W_m1 + (size_t)(ks * 128) * D_ + k;
        #pragma unroll 4
        for (int j = 0; j < 128; j++) {
            const float wv = __ldg(&Wb[(size_t)j * D_]);
            #pragma unroll
            for (int bb = 0; bb < 8; bb++) acc[bb] += s_a[bb][j] * wv;
        }
        #pragma unroll
        for (int bb = 0; bb < 8; bb++)
            g_m1p[ks][(size_t)(bg * 8 + bb) * D_ + k] = acc[bb];
        block_signal(&c_m1);
        return;
    }

    // ================= m1@W_m2 GEMM (split-K 8, 64-wide); waits on m1 =================
    if (bid < BID_TILE) {
        block_wait(&c_m1, 256);
        const int idx = bid - BID_F2;
        const int ks = idx & 7, bg = (idx >> 3) & 15, st = idx >> 7;
        const int k = st * 256 + tid;
        float (*s_m1)[64] = reinterpret_cast<float (*)[64]>(sbuf);
        for (int i = tid; i < 8 * 64; i += 256) {
            const int bb = i >> 6, j = i & 63;
            const int jj = ks * 64 + j;
            const int b = bg * 8 + bb;
            float m1 = b_m1[jj];
            #pragma unroll
            for (int p = 0; p < M1_KS; p++) m1 += g_m1p[p][(size_t)b * D_ + jj];
            s_m1[bb][j] = m1;
        }
        __syncthreads();
        float acc[8] = {};
        const float* Wb = W_m2 + (size_t)(ks * 64) * D_ + k;
        #pragma unroll 4
        for (int j = 0; j < 64; j++) {
            const float wv = __ldg(&Wb[(size_t)j * D_]);
            #pragma unroll
            for (int bb = 0; bb < 8; bb++) acc[bb] += s_m1[bb][j] * wv;
        }
        #pragma unroll
        for (int bb = 0; bb < 8; bb++)
            g_f2p[ks][(size_t)(bg * 8 + bb) * D_ + k] = acc[bb];
        block_signal(&c_f2);
        return;
    }

    // ================= fused logits+msa tile (the 1.07 GB stream) =================
    if (bid < BID_FS) {
        // carve: [0,512) c*W_ca (float4[128]); [512,640) logits; [640,768) weights; [768] red
        float4* s_cw    = reinterpret_cast<float4*>(sbuf);
        float*  s_logit = sbuf + 512;
        float*  s_w     = sbuf + 640;
        float*  s_red   = sbuf + 768;

        const int idx = bid - BID_TILE;
        const int b = idx >> 4, s = idx & 15;
        const int warp = tid >> 5, lane = tid & 31;
        const float* cbase = past + (size_t)b * T_ * (2 * D_) + (size_t)s * TS * (2 * D_);

        if (tid < D_ / 4) {
            float4 c = reinterpret_cast<const float4*>(control + (size_t)b * D_)[tid];
            float4 w = reinterpret_cast<const float4*>(W_ca)[tid];
            s_cw[tid] = make_float4(c.x * w.x, c.y * w.y, c.z * w.z, c.w * w.w);
        }
        __syncthreads();

        // --- phase A: 128 logits (8 warps x 16 t, two groups of 8 for MLP) ---
        const float bias = b_ca[0];
        #pragma unroll
        for (int g = 0; g < 2; g++) {
            const int t0 = warp * 16 + g * 8;
            float acc[8] = {};
            #pragma unroll
            for (int j = 0; j < 4; j++) {
                const float4 c = s_cw[lane + j * 32];
                #pragma unroll
                for (int i = 0; i < 8; i++) {
                    float4 v = reinterpret_cast<const float4*>(
                                   cbase + (size_t)(t0 + i) * (2 * D_))[lane + j * 32];
                    acc[i] += v.x * c.x + v.y * c.y + v.z * c.z + v.w * c.w;
                }
            }
            #pragma unroll
            for (int i = 0; i < 8; i++) {
                float a = acc[i];
                #pragma unroll
                for (int o = 16; o; o >>= 1) a += __shfl_xor_sync(0xffffffffu, a, o);
                if (lane == 0) s_logit[t0 + i] = a + bias;
            }
        }
        __syncthreads();

        // --- local softmax stats (warp 0) ---
        if (warp == 0) {
            float v[4], m = -3.4e38f;
            #pragma unroll
            for (int q = 0; q < 4; q++) {
                float x = s_logit[lane + q * 32];
                if (x == 0.f) x = -1e9f;              // padding mask
                v[q] = x;
                m = fmaxf(m, x);
            }
            #pragma unroll
            for (int o = 16; o; o >>= 1) m = fmaxf(m, __shfl_xor_sync(0xffffffffu, m, o));
            float sum = 0.f;
            #pragma unroll
            for (int q = 0; q < 4; q++) sum += expf(v[q] - m);
            #pragma unroll
            for (int o = 16; o; o >>= 1) sum += __shfl_xor_sync(0xffffffffu, sum, o);
            if (lane == 0) { s_red[0] = m; g_stats[b * SPL + s] = make_float2(m, sum); }
        }
        __syncthreads();
        const float mx = s_red[0];
        if (tid < TS) {
            float x = s_logit[tid];
            if (x == 0.f) x = -1e9f;
            s_w[tid] = expf(x - mx);                  // unnormalized weight
        }
        __syncthreads();

        // --- phase B: weighted sum of memories half (float2, ILP 4) ---
        const float2* mbase = reinterpret_cast<const float2*>(cbase + D_);
        float2 a0 = {0,0}, a1 = {0,0}, a2 = {0,0}, a3 = {0,0};
        #pragma unroll 4
        for (int t = 0; t < TS; t += 4) {
            float2 v0 = mbase[(size_t)(t + 0) * D_ + tid];
            float2 v1 = mbase[(size_t)(t + 1) * D_ + tid];
            float2 v2 = mbase[(size_t)(t + 2) * D_ + tid];
            float2 v3 = mbase[(size_t)(t + 3) * D_ + tid];
            const float w0 = s_w[t], w1 = s_w[t + 1], w2 = s_w[t + 2], w3 = s_w[t + 3];
            a0.x += w0 * v0.x; a0.y += w0 * v0.y;
            a1.x += w1 * v1.x; a1.y += w1 * v1.y;
            a2.x += w2 * v2.x; a2.y += w2 * v2.y;
            a3.x += w3 * v3.x; a3.y += w3 * v3.y;
        }
        float2 acc = make_float2((a0.x + a1.x) + (a2.x + a3.x),
                                 (a0.y + a1.y) + (a2.y + a3.y));
        reinterpret_cast<float2*>(g_part + (size_t)(b * SPL + s) * D_)[tid] = acc;
        block_signal(&c_tile);
        return;
    }

    // ================= msa@W_s GEMM (split-K 16, 32-wide); waits on stream =================
    if (bid < BID_EPI) {
        block_wait(&c_tile, B_ * SPL);
        const int idx = bid - BID_FS;
        const int ks = idx & 15, bg = (idx >> 4) & 15, st = idx >> 8;
        const int k = st * 256 + tid;

        float (*s_msa)[32]   = reinterpret_cast<float (*)[32]>(sbuf);          // 8*32
        float (*s_scale)[16] = reinterpret_cast<float (*)[16]>(sbuf + 8 * 128); // 8*16

        // inline softmax rescale factors from g_stats (one thread per batch row)
        if (tid < 8) {
            const int b = bg * 8 + tid;
            float m[SPL], sm[SPL], gm = -3.4e38f;
            #pragma unroll
            for (int sp = 0; sp < SPL; sp++) {
                float2 stv = g_stats[b * SPL + sp];
                m[sp] = stv.x; sm[sp] = stv.y;
                gm = fmaxf(gm, stv.x);
            }
            float tot = 0.f;
            #pragma unroll
            for (int sp = 0; sp < SPL; sp++) tot += sm[sp] * expf(m[sp] - gm);
            const float inv = 1.f / tot;
            #pragma unroll
            for (int sp = 0; sp < SPL; sp++) s_scale[tid][sp] = expf(m[sp] - gm) * inv;
        }
        __syncthreads();

        for (int i = tid; i < 8 * 32; i += 256) {
            const int bb = i >> 5, j = i & 31;
            const int jj = ks * 32 + j;
            const int b = bg * 8 + bb;
            float ms = 0.f;
            #pragma unroll
            for (int sp = 0; sp < SPL; sp++)
                ms += g_part[(size_t)(b * SPL + sp) * D_ + jj] * s_scale[bb][sp];
            s_msa[bb][j] = ms;
        }
        __syncthreads();
        float acc[8] = {};
        const float* Wb = W_s + (size_t)(ks * 32) * D_ + k;
        #pragma unroll 4
        for (int j = 0; j < 32; j++) {
            const float wv = __ldg(&Wb[(size_t)j * D_]);
            #pragma unroll
            for (int bb = 0; bb < 8; bb++) acc[bb] += s_msa[bb][j] * wv;
        }
        #pragma unroll
        for (int bb = 0; bb < 8; bb++)
            g_fsp[ks][(size_t)(bg * 8 + bb) * D_ + k] = acc[bb];
        block_signal(&c_fs);
        return;
    }

    // ================= epilogue =================
    {
        block_wait(&c_f2, 257);
        block_wait(&c_fs, 512);
        const int b = bid - BID_EPI;
        // 256 threads, 2 columns each
        #pragma unroll
        for (int h = 0; h < 2; h++) {
            const int k = tid + h * 256;
            float acc = b_m2[k] + b_s[k];
            #pragma unroll
            for (int p = 0; p < F2_KS; p++) acc += g_f2p[p][(size_t)b * D_ + k];
            #pragma unroll
            for (int p = 0; p < FS_KS; p++) acc += g_fsp[p][(size_t)b * D_ + k];
            const float g = g_gate[b];
            out[(size_t)b * D_ + k] = acc * g + (1.f - g) * memory[(size_t)b * D_ + k];
        }
        // last finisher resets counters for the next (graph-replayed) run
        __threadfence();
        __syncthreads();
        if (tid == 0) {
            int old = atomicAdd(&c_epi, 1);
            if (old == B_ - 1) {
                c_m1 = 0; c_tile = 0; c_f2 = 0; c_fs = 0; c_epi = 0;
                __threadfence();
            }
        }
    }
}

// ---------------- launch ----------------
extern "C" void kernel_launch(void* const* d_in, const int* in_sizes, int n_in,
                              void* d_out, int out_size)
{
    const float* memory  = (const float*)d_in[0];
    const float* read    = (const float*)d_in[1];
    const float* control = (const float*)d_in[2];
    const float* past    = (const float*)d_in[3];
    const float* W_m1    = (const float*)d_in[4];
    const float* b_m1    = (const float*)d_in[5];
    const float* W_ca    = (const float*)d_in[6];
    const float* b_ca    = (const float*)d_in[7];
    const float* W_m2    = (const float*)d_in[8];
    const float* b_m2    = (const float*)d_in[9];
    const float* W_s     = (const float*)d_in[10];
    const float* b_s     = (const float*)d_in[11];
    const float* W_m3    = (const float*)d_in[12];
    const float* b_m3    = (const float*)d_in[13];
    float* out = (float*)d_out;

    kmain<<<GRID_TOTAL, 256>>>(past, control, W_ca, b_ca, memory, read,
                               W_m1, b_m1, W_m2, b_m2, W_s, b_s, W_m3, b_m3, out);
}